// round 15
// baseline (speedup 1.0000x reference)
#include <cuda_runtime.h>
#include <cuda_bf16.h>
#include <math.h>
#include <stdint.h>

#define Bq 8
#define Sq 2048
#define Eq 128
#define Hq 8
#define HSq 16
#define BSROWS (Bq * Sq)
#define NBH 64
#define NT 16

typedef unsigned long long u64;
typedef unsigned int u32;

#define QSCALE 5.770780163555854f   // 4 * log2(e), folded into Q

__device__ __forceinline__ float ex2f(float x) {
    float y; asm("ex2.approx.f32 %0, %1;" : "=f"(y) : "f"(x)); return y;
}
__device__ __forceinline__ u32 cvt_bf16x2(float even, float odd) {
    u32 r; asm("cvt.rn.satfinite.bf16x2.f32 %0, %1, %2;" : "=r"(r) : "f"(odd), "f"(even));
    return r;  // low half = even
}
__device__ __forceinline__ void split_pack(float x, float y, u32& hp, u32& lp) {
    float hx = __bfloat162float(__float2bfloat16(x));
    float hy = __bfloat162float(__float2bfloat16(y));
    hp = cvt_bf16x2(hx, hy);
    lp = cvt_bf16x2(x - hx, y - hy);
}
__device__ __forceinline__ void mma_bf16(float* c, const u32* a, u32 b0, u32 b1) {
    asm volatile("mma.sync.aligned.m16n8k16.row.col.f32.bf16.bf16.f32 "
                 "{%0,%1,%2,%3}, {%4,%5,%6,%7}, {%8,%9}, {%0,%1,%2,%3};"
                 : "+f"(c[0]), "+f"(c[1]), "+f"(c[2]), "+f"(c[3])
                 : "r"(a[0]), "r"(a[1]), "r"(a[2]), "r"(a[3]), "r"(b0), "r"(b1));
}
__device__ __forceinline__ u32 smem_u32(const void* p) {
    u32 a; asm("{ .reg .u64 t; cvta.to.shared.u64 t, %1; cvt.u32.u64 %0, t; }" : "=r"(a) : "l"(p));
    return a;
}
__device__ __forceinline__ void cp_async16(u32 dst, const void* src) {
    asm volatile("cp.async.cg.shared.global [%0], [%1], 16;" :: "r"(dst), "l"(src) : "memory");
}
__device__ __forceinline__ void cp_commit() {
    asm volatile("cp.async.commit_group;" ::: "memory");
}
__device__ __forceinline__ void cp_wait0() {
    asm volatile("cp.async.wait_group 0;" ::: "memory");
}

// ---- Scratch (device globals) ----
__device__ __align__(16) u32 g_wh[4 * 8192];        // W split: m:0=Wq,1=Wk,2=Wv,3=Wp
__device__ __align__(16) u32 g_wl[4 * 8192];
__device__ __align__(16) u32 g_qh[NBH * Sq * 8];    // Q hi [bh][s][8 u32], QSCALE folded
__device__ __align__(16) u32 g_ql[NBH * Sq * 8];
__device__ __align__(16) u32 g_kf[NBH * Sq * 16];   // K fused: [bh][s][16 u32]
__device__ __align__(16) u32 g_vf[NBH * NT * 2048]; // V fused: [bh][tile][2048 u32]
__device__ float g_a[BSROWS * Eq];                  // attn out fp32

// ---------------------------------------------------------------------------
// Prep: split weights into bf16 hi/lo pair layout.
// ---------------------------------------------------------------------------
__global__ __launch_bounds__(256) void split_w(
    const float* __restrict__ Wq, const float* __restrict__ Wk,
    const float* __restrict__ Wv, const float* __restrict__ Wp)
{
    const int i = blockIdx.x * 256 + threadIdx.x;
    const int m = i >> 13, j = i & 8191;
    const float* src = (m == 0) ? Wq : (m == 1) ? Wk : (m == 2) ? Wv : Wp;
    float2 v = ((const float2*)src)[j];
    split_pack(v.x, v.y, g_wh[i], g_wl[i]);
}

// ---------------------------------------------------------------------------
// HMMA GEMM building blocks.
// ---------------------------------------------------------------------------
__device__ __forceinline__ void load_B(u32* sBh, u32* sBl, int wsrc, int tid)
{
    #pragma unroll
    for (int i = 0; i < 8; ++i) {
        const int idx = tid + i * 256;
        const int col = idx >> 4, q = idx & 15;
        *(float4*)&sBh[col * 68 + q * 4] = ((const float4*)(g_wh + wsrc * 8192))[idx];
        *(float4*)&sBl[col * 68 + q * 4] = ((const float4*)(g_wl + wsrc * 8192))[idx];
    }
    __syncthreads();
}

__device__ __forceinline__ void load_A_f32(
    const float* __restrict__ A, int r0, int r1, int c,
    u32 ah[8][4], u32 al[8][4])
{
    const float2* A0 = (const float2*)&A[(size_t)r0 * Eq];
    const float2* A1 = (const float2*)&A[(size_t)r1 * Eq];
    #pragma unroll
    for (int kk = 0; kk < 8; ++kk) {
        float2 f;
        f = A0[kk * 8 + c];     split_pack(f.x, f.y, ah[kk][0], al[kk][0]);
        f = A1[kk * 8 + c];     split_pack(f.x, f.y, ah[kk][1], al[kk][1]);
        f = A0[kk * 8 + c + 4]; split_pack(f.x, f.y, ah[kk][2], al[kk][2]);
        f = A1[kk * 8 + c + 4]; split_pack(f.x, f.y, ah[kk][3], al[kk][3]);
    }
}

__device__ __forceinline__ void gemm_mainloop(
    const u32* sBh, const u32* sBl,
    u32 ah[8][4], u32 al[8][4], float acc[16][4], int lane)
{
    const int g = lane >> 2, c = lane & 3;
    #pragma unroll
    for (int n = 0; n < 16; ++n) {
        acc[n][0] = acc[n][1] = acc[n][2] = acc[n][3] = 0.0f;
        const int base = (n * 8 + g) * 68;
        #pragma unroll
        for (int kk = 0; kk < 8; ++kk) {
            const u32 bh0 = sBh[base + kk * 8 + c];
            const u32 bh1 = sBh[base + kk * 8 + c + 4];
            const u32 bl0 = sBl[base + kk * 8 + c];
            const u32 bl1 = sBl[base + kk * 8 + c + 4];
            mma_bf16(acc[n], ah[kk], bh0, bh1);
            mma_bf16(acc[n], al[kk], bh0, bh1);
            mma_bf16(acc[n], ah[kk], bl0, bl1);
        }
    }
}

// QKV: grid (128, 3). A fetched BEFORE B staging to hide global latency.
__global__ __launch_bounds__(256) void hmma_qkv(const float* __restrict__ x)
{
    extern __shared__ u32 smem[];
    u32* sBh = smem;
    u32* sBl = smem + 128 * 68;

    const int tid = threadIdx.x, wid = tid >> 5, lane = tid & 31;
    const int g = lane >> 2, c = lane & 3;
    const int wz = blockIdx.y;
    const int row0 = blockIdx.x * 128 + wid * 16;

    const int r0 = row0 + g, r1 = row0 + g + 8;
    u32 ah[8][4], al[8][4];
    load_A_f32(x, r0, r1, c, ah, al);

    load_B(sBh, sBl, wz, tid);

    float acc[16][4];
    gemm_mainloop(sBh, sBl, ah, al, acc, lane);

    const int b = row0 >> 11;
    const int s0 = (row0 & 2047) + g, s1 = s0 + 8;

    #pragma unroll
    for (int n = 0; n < 16; ++n) {
        float v0x = acc[n][0], v0y = acc[n][1], v1x = acc[n][2], v1y = acc[n][3];
        if (wz == 0) { v0x *= QSCALE; v0y *= QSCALE; v1x *= QSCALE; v1y *= QSCALE; }
        const int h = n >> 1;
        const int bh = b * Hq + h;
        if (wz == 0) {
            u32 hp, lp;
            const u32 j = (u32)((n & 1) * 4 + c);
            split_pack(v0x, v0y, hp, lp);
            g_qh[((size_t)bh * Sq + s0) * 8 + j] = hp;
            g_ql[((size_t)bh * Sq + s0) * 8 + j] = lp;
            split_pack(v1x, v1y, hp, lp);
            g_qh[((size_t)bh * Sq + s1) * 8 + j] = hp;
            g_ql[((size_t)bh * Sq + s1) * 8 + j] = lp;
        } else if (wz == 1) {
            u32 hp, lp;
            const u32 slot = (u32)(c * 4 + (n & 1));
            split_pack(v0x, v0y, hp, lp);
            g_kf[((size_t)bh * Sq + s0) * 16 + slot] = hp;
            g_kf[((size_t)bh * Sq + s0) * 16 + slot + 2] = lp;
            split_pack(v1x, v1y, hp, lp);
            g_kf[((size_t)bh * Sq + s1) * 16 + slot] = hp;
            g_kf[((size_t)bh * Sq + s1) * 16 + slot + 2] = lp;
        } else {
            __nv_bfloat16* vbase = (__nv_bfloat16*)(g_vf + (size_t)bh * (NT * 2048));
            const int d0 = (n & 1) * 8 + 2 * c;
            #pragma unroll
            for (int rr = 0; rr < 2; ++rr) {
                const int s = rr ? s1 : s0;
                const float vx = rr ? v1x : v0x, vy = rr ? v1y : v0y;
                const int p = s >> 1, par = s & 1;
                const int q = p & 63;
                const int kk = q >> 3, role = (q >> 2) & 1, cc = q & 3;
                const u32 tbase = (u32)(p >> 6) * 2048;
                #pragma unroll
                for (int dd = 0; dd < 2; ++dd) {
                    const int d = d0 + dd;
                    const float v = dd ? vy : vx;
                    const int half = d >> 3, gg = d & 7;
                    const u32 idx = tbase + (u32)((kk * 64 + half * 32 + gg * 4 + cc) * 4 + role);
                    __nv_bfloat16 hi = __float2bfloat16(v);
                    vbase[(size_t)idx * 2 + par] = hi;
                    vbase[(size_t)(idx + 2) * 2 + par] =
                        __float2bfloat16(v - __bfloat162float(hi));
                }
            }
        }
    }
}

// Output projection: grid (128, 2); A fetched BEFORE B staging.
__global__ __launch_bounds__(256) void hmma_proj(
    const float* __restrict__ bias, float* __restrict__ out)
{
    extern __shared__ u32 smem[];
    u32* sBh = smem;
    u32* sBl = smem + 64 * 68;

    const int tid = threadIdx.x, wid = tid >> 5, lane = tid & 31;
    const int g = lane >> 2, c = lane & 3;
    const int row0 = blockIdx.x * 128 + wid * 16;
    const int col0 = blockIdx.y * 64;

    const int r0 = row0 + g, r1 = row0 + g + 8;
    u32 ah[8][4], al[8][4];
    load_A_f32(g_a, r0, r1, c, ah, al);

    // load 64 columns of Wp (hi+lo)
    {
        const float4* wh = (const float4*)(g_wh + 3 * 8192 + col0 * 64);
        const float4* wl = (const float4*)(g_wl + 3 * 8192 + col0 * 64);
        #pragma unroll
        for (int i = 0; i < 4; ++i) {
            const int idx = tid + i * 256;
            const int col = idx >> 4, q = idx & 15;
            *(float4*)&sBh[col * 68 + q * 4] = wh[idx];
            *(float4*)&sBl[col * 68 + q * 4] = wl[idx];
        }
        __syncthreads();
    }

    float acc[8][4];
    #pragma unroll
    for (int n = 0; n < 8; ++n) {
        acc[n][0] = acc[n][1] = acc[n][2] = acc[n][3] = 0.0f;
        const int base = (n * 8 + g) * 68;
        #pragma unroll
        for (int kk = 0; kk < 8; ++kk) {
            const u32 bh0 = sBh[base + kk * 8 + c];
            const u32 bh1 = sBh[base + kk * 8 + c + 4];
            const u32 bl0 = sBl[base + kk * 8 + c];
            const u32 bl1 = sBl[base + kk * 8 + c + 4];
            mma_bf16(acc[n], ah[kk], bh0, bh1);
            mma_bf16(acc[n], al[kk], bh0, bh1);
            mma_bf16(acc[n], ah[kk], bl0, bl1);
        }
    }

    #pragma unroll
    for (int n = 0; n < 8; ++n) {
        const int col = col0 + n * 8 + 2 * c;
        const float2 bb = *(const float2*)&bias[col];
        float2 v0 = make_float2(acc[n][0] + bb.x, acc[n][1] + bb.y);
        float2 v1 = make_float2(acc[n][2] + bb.x, acc[n][3] + bb.y);
        *(float2*)&out[(size_t)r0 * Eq + col] = v0;
        *(float2*)&out[(size_t)r1 * Eq + col] = v1;
    }
}

// ---------------------------------------------------------------------------
// HMMA flash attention: fixed-m softmax, cp.async double buffering, one
// barrier per tile, half-tile processing with WARP-STAGGERED half order
// (odd warps run halves B,A) so tensor and MUFU phases overlap across warps.
// m is taken from each warp's first processed chunk of tile 0.
// grid (16, 64), 256 threads, 2 CTAs/SM.
// ---------------------------------------------------------------------------
__global__ __launch_bounds__(256, 2) void attn_mma()
{
    __shared__ __align__(16) u32 sK[2][2048];
    __shared__ __align__(16) u32 sV[2][2048];

    const int tid = threadIdx.x;
    const int lane = tid & 31, wid = tid >> 5;
    const int g = lane >> 2, c = lane & 3;
    const int bh = blockIdx.y;
    const int q0 = blockIdx.x * 128;
    const int rowbase = q0 + wid * 16;
    const int worder = wid & 1;

    u32 qh[4], qlo[4];
    {
        const u32* ph = g_qh + ((size_t)bh * Sq + rowbase) * 8;
        const u32* pl = g_ql + ((size_t)bh * Sq + rowbase) * 8;
        qh[0] = ph[g * 8 + c];       qh[1] = ph[(g + 8) * 8 + c];
        qh[2] = ph[g * 8 + c + 4];   qh[3] = ph[(g + 8) * 8 + c + 4];
        qlo[0] = pl[g * 8 + c];      qlo[1] = pl[(g + 8) * 8 + c];
        qlo[2] = pl[g * 8 + c + 4];  qlo[3] = pl[(g + 8) * 8 + c + 4];
    }

    float o[3][4];
    #pragma unroll
    for (int n = 0; n < 3; ++n)
        #pragma unroll
        for (int i = 0; i < 4; ++i) o[n][i] = 0.0f;
    float m0 = 0.0f, m1 = 0.0f;

    const u32 b_one = (g == 0) ? 0x3F803F80u : 0u;

    const float4* skf = (const float4*)(g_kf + (size_t)bh * Sq * 16);
    const float4* svf = (const float4*)(g_vf + (size_t)bh * (NT * 2048));
    const u32 skb = smem_u32(sK), svb = smem_u32(sV);

    cp_async16(skb + (u32)tid * 16,          skf + tid);
    cp_async16(skb + (u32)(tid + 256) * 16,  skf + tid + 256);
    cp_async16(svb + (u32)tid * 16,          svf + tid);
    cp_async16(svb + (u32)(tid + 256) * 16,  svf + tid + 256);
    cp_commit();

    for (int kt = 0; kt < NT; ++kt) {
        const int buf = kt & 1;
        cp_wait0();
        __syncthreads();
        if (kt + 1 < NT) {
            const u32 kdst = skb + (u32)(buf ^ 1) * 8192;
            const u32 vdst = svb + (u32)(buf ^ 1) * 8192;
            const int soff = (kt + 1) * 512;
            cp_async16(kdst + (u32)tid * 16,         skf + soff + tid);
            cp_async16(kdst + (u32)(tid + 256) * 16, skf + soff + tid + 256);
            cp_async16(vdst + (u32)tid * 16,         svf + soff + tid);
            cp_async16(vdst + (u32)(tid + 256) * 16, svf + soff + tid + 256);
            cp_commit();
        }

        #pragma unroll
        for (int hi = 0; hi < 2; ++hi) {
            const int half = hi ^ worder;   // odd warps run halves in reverse
            // ---- QK scores: 8 n-tiles ----
            float sc[8][4];
            #pragma unroll
            for (int n = 0; n < 8; ++n) {
                sc[n][0] = sc[n][1] = sc[n][2] = sc[n][3] = 0.0f;
                const int nn = half * 8 + n;
                const uint4 kv = *(const uint4*)&sK[buf][(nn * 8 + g) * 16 + c * 4];
                mma_bf16(sc[n], qh, kv.x, kv.y);
                mma_bf16(sc[n], qlo, kv.x, kv.y);
                mma_bf16(sc[n], qh, kv.z, kv.w);
            }

            if (kt == 0 && hi == 0) {
                // per-row reference max over this warp's first 64 keys
                float mx0 = sc[0][0], mx1 = sc[0][2];
                #pragma unroll
                for (int n = 0; n < 8; ++n) {
                    mx0 = fmaxf(mx0, fmaxf(sc[n][0], sc[n][1]));
                    mx1 = fmaxf(mx1, fmaxf(sc[n][2], sc[n][3]));
                }
                mx0 = fmaxf(mx0, __shfl_xor_sync(0xffffffffu, mx0, 1));
                mx0 = fmaxf(mx0, __shfl_xor_sync(0xffffffffu, mx0, 2));
                mx1 = fmaxf(mx1, __shfl_xor_sync(0xffffffffu, mx1, 1));
                mx1 = fmaxf(mx1, __shfl_xor_sync(0xffffffffu, mx1, 2));
                m0 = mx0; m1 = mx1;
            }

            // ---- exp + convert ----
            #pragma unroll
            for (int n = 0; n < 8; ++n) {
                sc[n][0] = ex2f(sc[n][0] - m0);
                sc[n][1] = ex2f(sc[n][1] - m0);
                sc[n][2] = ex2f(sc[n][2] - m1);
                sc[n][3] = ex2f(sc[n][3] - m1);
            }
            u32 pf[4][4];
            #pragma unroll
            for (int k2 = 0; k2 < 4; ++k2) {
                pf[k2][0] = cvt_bf16x2(sc[2*k2][0],   sc[2*k2][1]);
                pf[k2][1] = cvt_bf16x2(sc[2*k2][2],   sc[2*k2][3]);
                pf[k2][2] = cvt_bf16x2(sc[2*k2+1][0], sc[2*k2+1][1]);
                pf[k2][3] = cvt_bf16x2(sc[2*k2+1][2], sc[2*k2+1][3]);
            }

            // ---- PV: 4 kk, ones column accumulates l ----
            #pragma unroll
            for (int k2 = 0; k2 < 4; ++k2) {
                const int kk = half * 4 + k2;
                const uint4 v0 = *(const uint4*)&sV[buf][(kk * 64 + g * 4 + c) * 4];
                const uint4 v1 = *(const uint4*)&sV[buf][(kk * 64 + 32 + g * 4 + c) * 4];
                mma_bf16(o[0], pf[k2], v0.x, v0.y);
                mma_bf16(o[0], pf[k2], v0.z, v0.w);
                mma_bf16(o[1], pf[k2], v1.x, v1.y);
                mma_bf16(o[1], pf[k2], v1.z, v1.w);
                mma_bf16(o[2], pf[k2], b_one, b_one);
            }
        }
        // no trailing barrier: next-tile writes target buf^1 and are issued
        // only after the next top-of-loop barrier.
    }

    const float l0 = __shfl_sync(0xffffffffu, o[2][0], lane & ~3);
    const float l1 = __shfl_sync(0xffffffffu, o[2][2], lane & ~3);
    const float i0 = 1.0f / l0, i1 = 1.0f / l1;
    const int b = bh >> 3, h = bh & 7;
    const int s0 = rowbase + g, s1 = rowbase + g + 8;
    #pragma unroll
    for (int n = 0; n < 2; ++n) {
        const int col = h * 16 + n * 8 + 2 * c;
        float2 v0 = make_float2(o[n][0] * i0, o[n][1] * i0);
        float2 v1 = make_float2(o[n][2] * i1, o[n][3] * i1);
        *(float2*)&g_a[((size_t)b * Sq + s0) * Eq + col] = v0;
        *(float2*)&g_a[((size_t)b * Sq + s1) * Eq + col] = v1;
    }
}

// ---------------------------------------------------------------------------
// Launch. Inputs: x, Wk, Wq, Wv, Wp, bp. Output: float32.
// ---------------------------------------------------------------------------
#define GEMM_SMEM (2 * 128 * 68 * 4)
#define PROJ_SMEM (2 * 64 * 68 * 4)

extern "C" void kernel_launch(void* const* d_in, const int* in_sizes, int n_in,
                              void* d_out, int out_size)
{
    const float* x  = (const float*)d_in[0];
    const float* Wk = (const float*)d_in[1];
    const float* Wq = (const float*)d_in[2];
    const float* Wv = (const float*)d_in[3];
    const float* Wp = (const float*)d_in[4];
    const float* bp = (const float*)d_in[5];
    float* out = (float*)d_out;

    cudaFuncSetAttribute(hmma_qkv, cudaFuncAttributeMaxDynamicSharedMemorySize, GEMM_SMEM);
    cudaFuncSetAttribute(hmma_proj, cudaFuncAttributeMaxDynamicSharedMemorySize, PROJ_SMEM);

    split_w<<<128, 256>>>(Wq, Wk, Wv, Wp);
    hmma_qkv<<<dim3(BSROWS / 128, 3), 256, GEMM_SMEM>>>(x);
    attn_mma<<<dim3(Sq / 128, NBH), 256>>>();
    hmma_proj<<<dim3(BSROWS / 128, 2), 256, PROJ_SMEM>>>(bp, out);
}

// round 16
// speedup vs baseline: 1.0393x; 1.0393x over previous
#include <cuda_runtime.h>
#include <cuda_bf16.h>
#include <math.h>
#include <stdint.h>

#define Bq 8
#define Sq 2048
#define Eq 128
#define Hq 8
#define HSq 16
#define BSROWS (Bq * Sq)
#define NBH 64
#define NT 16

typedef unsigned long long u64;
typedef unsigned int u32;

#define QSCALE 5.770780163555854f   // 4 * log2(e), folded into Q

__device__ __forceinline__ float ex2f(float x) {
    float y; asm("ex2.approx.f32 %0, %1;" : "=f"(y) : "f"(x)); return y;
}
__device__ __forceinline__ u32 cvt_bf16x2(float even, float odd) {
    u32 r; asm("cvt.rn.satfinite.bf16x2.f32 %0, %1, %2;" : "=r"(r) : "f"(odd), "f"(even));
    return r;  // low half = even
}
__device__ __forceinline__ void split_pack(float x, float y, u32& hp, u32& lp) {
    float hx = __bfloat162float(__float2bfloat16(x));
    float hy = __bfloat162float(__float2bfloat16(y));
    hp = cvt_bf16x2(hx, hy);
    lp = cvt_bf16x2(x - hx, y - hy);
}
__device__ __forceinline__ void mma_bf16(float* c, const u32* a, u32 b0, u32 b1) {
    asm volatile("mma.sync.aligned.m16n8k16.row.col.f32.bf16.bf16.f32 "
                 "{%0,%1,%2,%3}, {%4,%5,%6,%7}, {%8,%9}, {%0,%1,%2,%3};"
                 : "+f"(c[0]), "+f"(c[1]), "+f"(c[2]), "+f"(c[3])
                 : "r"(a[0]), "r"(a[1]), "r"(a[2]), "r"(a[3]), "r"(b0), "r"(b1));
}
__device__ __forceinline__ u32 smem_u32(const void* p) {
    u32 a; asm("{ .reg .u64 t; cvta.to.shared.u64 t, %1; cvt.u32.u64 %0, t; }" : "=r"(a) : "l"(p));
    return a;
}
__device__ __forceinline__ void cp_async16(u32 dst, const void* src) {
    asm volatile("cp.async.cg.shared.global [%0], [%1], 16;" :: "r"(dst), "l"(src) : "memory");
}
__device__ __forceinline__ void cp_commit() {
    asm volatile("cp.async.commit_group;" ::: "memory");
}
__device__ __forceinline__ void cp_wait0() {
    asm volatile("cp.async.wait_group 0;" ::: "memory");
}

// ---- Scratch (device globals) ----
__device__ __align__(16) u32 g_wh[4 * 8192];        // W split: m:0=Wq,1=Wk,2=Wv,3=Wp
__device__ __align__(16) u32 g_wl[4 * 8192];
__device__ __align__(16) u32 g_qh[NBH * Sq * 8];    // Q hi [bh][s][8 u32], QSCALE folded
__device__ __align__(16) u32 g_ql[NBH * Sq * 8];
__device__ __align__(16) u32 g_kf[NBH * Sq * 16];   // K fused: [bh][s][16 u32]
__device__ __align__(16) u32 g_vf[NBH * NT * 2048]; // V fused: [bh][tile][2048 u32]
__device__ float g_a[BSROWS * Eq];                  // attn out fp32

// ---------------------------------------------------------------------------
// Prep: split weights into bf16 hi/lo pair layout.
// ---------------------------------------------------------------------------
__global__ __launch_bounds__(256) void split_w(
    const float* __restrict__ Wq, const float* __restrict__ Wk,
    const float* __restrict__ Wv, const float* __restrict__ Wp)
{
    const int i = blockIdx.x * 256 + threadIdx.x;
    const int m = i >> 13, j = i & 8191;
    const float* src = (m == 0) ? Wq : (m == 1) ? Wk : (m == 2) ? Wv : Wp;
    float2 v = ((const float2*)src)[j];
    split_pack(v.x, v.y, g_wh[i], g_wl[i]);
}

// ---------------------------------------------------------------------------
// HMMA GEMM building blocks.
// ---------------------------------------------------------------------------
__device__ __forceinline__ void load_B(u32* sBh, u32* sBl, int wsrc, int tid)
{
    #pragma unroll
    for (int i = 0; i < 8; ++i) {
        const int idx = tid + i * 256;
        const int col = idx >> 4, q = idx & 15;
        *(float4*)&sBh[col * 68 + q * 4] = ((const float4*)(g_wh + wsrc * 8192))[idx];
        *(float4*)&sBl[col * 68 + q * 4] = ((const float4*)(g_wl + wsrc * 8192))[idx];
    }
    __syncthreads();
}

__device__ __forceinline__ void load_A_f32(
    const float* __restrict__ A, int r0, int r1, int c,
    u32 ah[8][4], u32 al[8][4])
{
    const float2* A0 = (const float2*)&A[(size_t)r0 * Eq];
    const float2* A1 = (const float2*)&A[(size_t)r1 * Eq];
    #pragma unroll
    for (int kk = 0; kk < 8; ++kk) {
        float2 f;
        f = A0[kk * 8 + c];     split_pack(f.x, f.y, ah[kk][0], al[kk][0]);
        f = A1[kk * 8 + c];     split_pack(f.x, f.y, ah[kk][1], al[kk][1]);
        f = A0[kk * 8 + c + 4]; split_pack(f.x, f.y, ah[kk][2], al[kk][2]);
        f = A1[kk * 8 + c + 4]; split_pack(f.x, f.y, ah[kk][3], al[kk][3]);
    }
}

__device__ __forceinline__ void gemm_mainloop(
    const u32* sBh, const u32* sBl,
    u32 ah[8][4], u32 al[8][4], float acc[16][4], int lane)
{
    const int g = lane >> 2, c = lane & 3;
    #pragma unroll
    for (int n = 0; n < 16; ++n) {
        acc[n][0] = acc[n][1] = acc[n][2] = acc[n][3] = 0.0f;
        const int base = (n * 8 + g) * 68;
        #pragma unroll
        for (int kk = 0; kk < 8; ++kk) {
            const u32 bh0 = sBh[base + kk * 8 + c];
            const u32 bh1 = sBh[base + kk * 8 + c + 4];
            const u32 bl0 = sBl[base + kk * 8 + c];
            const u32 bl1 = sBl[base + kk * 8 + c + 4];
            mma_bf16(acc[n], ah[kk], bh0, bh1);
            mma_bf16(acc[n], al[kk], bh0, bh1);
            mma_bf16(acc[n], ah[kk], bl0, bl1);
        }
    }
}

// QKV: grid (128, 3). A fetched BEFORE B staging to hide global latency.
__global__ __launch_bounds__(256) void hmma_qkv(const float* __restrict__ x)
{
    extern __shared__ u32 smem[];
    u32* sBh = smem;
    u32* sBl = smem + 128 * 68;

    const int tid = threadIdx.x, wid = tid >> 5, lane = tid & 31;
    const int g = lane >> 2, c = lane & 3;
    const int wz = blockIdx.y;
    const int row0 = blockIdx.x * 128 + wid * 16;

    const int r0 = row0 + g, r1 = row0 + g + 8;
    u32 ah[8][4], al[8][4];
    load_A_f32(x, r0, r1, c, ah, al);

    load_B(sBh, sBl, wz, tid);

    float acc[16][4];
    gemm_mainloop(sBh, sBl, ah, al, acc, lane);

    const int b = row0 >> 11;
    const int s0 = (row0 & 2047) + g, s1 = s0 + 8;

    #pragma unroll
    for (int n = 0; n < 16; ++n) {
        float v0x = acc[n][0], v0y = acc[n][1], v1x = acc[n][2], v1y = acc[n][3];
        if (wz == 0) { v0x *= QSCALE; v0y *= QSCALE; v1x *= QSCALE; v1y *= QSCALE; }
        const int h = n >> 1;
        const int bh = b * Hq + h;
        if (wz == 0) {
            u32 hp, lp;
            const u32 j = (u32)((n & 1) * 4 + c);
            split_pack(v0x, v0y, hp, lp);
            g_qh[((size_t)bh * Sq + s0) * 8 + j] = hp;
            g_ql[((size_t)bh * Sq + s0) * 8 + j] = lp;
            split_pack(v1x, v1y, hp, lp);
            g_qh[((size_t)bh * Sq + s1) * 8 + j] = hp;
            g_ql[((size_t)bh * Sq + s1) * 8 + j] = lp;
        } else if (wz == 1) {
            u32 hp, lp;
            const u32 slot = (u32)(c * 4 + (n & 1));
            split_pack(v0x, v0y, hp, lp);
            g_kf[((size_t)bh * Sq + s0) * 16 + slot] = hp;
            g_kf[((size_t)bh * Sq + s0) * 16 + slot + 2] = lp;
            split_pack(v1x, v1y, hp, lp);
            g_kf[((size_t)bh * Sq + s1) * 16 + slot] = hp;
            g_kf[((size_t)bh * Sq + s1) * 16 + slot + 2] = lp;
        } else {
            __nv_bfloat16* vbase = (__nv_bfloat16*)(g_vf + (size_t)bh * (NT * 2048));
            const int d0 = (n & 1) * 8 + 2 * c;
            #pragma unroll
            for (int rr = 0; rr < 2; ++rr) {
                const int s = rr ? s1 : s0;
                const float vx = rr ? v1x : v0x, vy = rr ? v1y : v0y;
                const int p = s >> 1, par = s & 1;
                const int q = p & 63;
                const int kk = q >> 3, role = (q >> 2) & 1, cc = q & 3;
                const u32 tbase = (u32)(p >> 6) * 2048;
                #pragma unroll
                for (int dd = 0; dd < 2; ++dd) {
                    const int d = d0 + dd;
                    const float v = dd ? vy : vx;
                    const int half = d >> 3, gg = d & 7;
                    const u32 idx = tbase + (u32)((kk * 64 + half * 32 + gg * 4 + cc) * 4 + role);
                    __nv_bfloat16 hi = __float2bfloat16(v);
                    vbase[(size_t)idx * 2 + par] = hi;
                    vbase[(size_t)(idx + 2) * 2 + par] =
                        __float2bfloat16(v - __bfloat162float(hi));
                }
            }
        }
    }
}

// Output projection: grid (128, 2); A fetched BEFORE B staging.
__global__ __launch_bounds__(256) void hmma_proj(
    const float* __restrict__ bias, float* __restrict__ out)
{
    extern __shared__ u32 smem[];
    u32* sBh = smem;
    u32* sBl = smem + 64 * 68;

    const int tid = threadIdx.x, wid = tid >> 5, lane = tid & 31;
    const int g = lane >> 2, c = lane & 3;
    const int row0 = blockIdx.x * 128 + wid * 16;
    const int col0 = blockIdx.y * 64;

    const int r0 = row0 + g, r1 = row0 + g + 8;
    u32 ah[8][4], al[8][4];
    load_A_f32(g_a, r0, r1, c, ah, al);

    // load 64 columns of Wp (hi+lo)
    {
        const float4* wh = (const float4*)(g_wh + 3 * 8192 + col0 * 64);
        const float4* wl = (const float4*)(g_wl + 3 * 8192 + col0 * 64);
        #pragma unroll
        for (int i = 0; i < 4; ++i) {
            const int idx = tid + i * 256;
            const int col = idx >> 4, q = idx & 15;
            *(float4*)&sBh[col * 68 + q * 4] = wh[idx];
            *(float4*)&sBl[col * 68 + q * 4] = wl[idx];
        }
        __syncthreads();
    }

    float acc[8][4];
    #pragma unroll
    for (int n = 0; n < 8; ++n) {
        acc[n][0] = acc[n][1] = acc[n][2] = acc[n][3] = 0.0f;
        const int base = (n * 8 + g) * 68;
        #pragma unroll
        for (int kk = 0; kk < 8; ++kk) {
            const u32 bh0 = sBh[base + kk * 8 + c];
            const u32 bh1 = sBh[base + kk * 8 + c + 4];
            const u32 bl0 = sBl[base + kk * 8 + c];
            const u32 bl1 = sBl[base + kk * 8 + c + 4];
            mma_bf16(acc[n], ah[kk], bh0, bh1);
            mma_bf16(acc[n], al[kk], bh0, bh1);
            mma_bf16(acc[n], ah[kk], bl0, bl1);
        }
    }

    #pragma unroll
    for (int n = 0; n < 8; ++n) {
        const int col = col0 + n * 8 + 2 * c;
        const float2 bb = *(const float2*)&bias[col];
        float2 v0 = make_float2(acc[n][0] + bb.x, acc[n][1] + bb.y);
        float2 v1 = make_float2(acc[n][2] + bb.x, acc[n][3] + bb.y);
        *(float2*)&out[(size_t)r0 * Eq + col] = v0;
        *(float2*)&out[(size_t)r1 * Eq + col] = v1;
    }
}

// ---------------------------------------------------------------------------
// HMMA flash attention: fixed-m softmax, cp.async double buffering, one
// barrier per tile, QUARTER-tile chunks (4 n-tiles = 32 keys) to shrink the
// live register set and allow 3 CTAs/SM (24 warps) for latency hiding.
// m is taken from tile 0's first 32 keys (any per-row constant is valid;
// bf16 P absorbs the overshoot range).
// grid (16, 64), 256 threads, 3 CTAs/SM.
// ---------------------------------------------------------------------------
__global__ __launch_bounds__(256, 3) void attn_mma()
{
    __shared__ __align__(16) u32 sK[2][2048];
    __shared__ __align__(16) u32 sV[2][2048];

    const int tid = threadIdx.x;
    const int lane = tid & 31, wid = tid >> 5;
    const int g = lane >> 2, c = lane & 3;
    const int bh = blockIdx.y;
    const int q0 = blockIdx.x * 128;
    const int rowbase = q0 + wid * 16;

    u32 qh[4], qlo[4];
    {
        const u32* ph = g_qh + ((size_t)bh * Sq + rowbase) * 8;
        const u32* pl = g_ql + ((size_t)bh * Sq + rowbase) * 8;
        qh[0] = ph[g * 8 + c];       qh[1] = ph[(g + 8) * 8 + c];
        qh[2] = ph[g * 8 + c + 4];   qh[3] = ph[(g + 8) * 8 + c + 4];
        qlo[0] = pl[g * 8 + c];      qlo[1] = pl[(g + 8) * 8 + c];
        qlo[2] = pl[g * 8 + c + 4];  qlo[3] = pl[(g + 8) * 8 + c + 4];
    }

    float o[3][4];
    #pragma unroll
    for (int n = 0; n < 3; ++n)
        #pragma unroll
        for (int i = 0; i < 4; ++i) o[n][i] = 0.0f;
    float m0 = 0.0f, m1 = 0.0f;

    const u32 b_one = (g == 0) ? 0x3F803F80u : 0u;

    const float4* skf = (const float4*)(g_kf + (size_t)bh * Sq * 16);
    const float4* svf = (const float4*)(g_vf + (size_t)bh * (NT * 2048));
    const u32 skb = smem_u32(sK), svb = smem_u32(sV);

    cp_async16(skb + (u32)tid * 16,          skf + tid);
    cp_async16(skb + (u32)(tid + 256) * 16,  skf + tid + 256);
    cp_async16(svb + (u32)tid * 16,          svf + tid);
    cp_async16(svb + (u32)(tid + 256) * 16,  svf + tid + 256);
    cp_commit();

    for (int kt = 0; kt < NT; ++kt) {
        const int buf = kt & 1;
        cp_wait0();
        __syncthreads();
        if (kt + 1 < NT) {
            const u32 kdst = skb + (u32)(buf ^ 1) * 8192;
            const u32 vdst = svb + (u32)(buf ^ 1) * 8192;
            const int soff = (kt + 1) * 512;
            cp_async16(kdst + (u32)tid * 16,         skf + soff + tid);
            cp_async16(kdst + (u32)(tid + 256) * 16, skf + soff + tid + 256);
            cp_async16(vdst + (u32)tid * 16,         svf + soff + tid);
            cp_async16(vdst + (u32)(tid + 256) * 16, svf + soff + tid + 256);
            cp_commit();
        }

        #pragma unroll
        for (int ch = 0; ch < 4; ++ch) {
            // ---- QK scores: 4 n-tiles (32 keys) ----
            float sc[4][4];
            #pragma unroll
            for (int n = 0; n < 4; ++n) {
                sc[n][0] = sc[n][1] = sc[n][2] = sc[n][3] = 0.0f;
                const int nn = ch * 4 + n;
                const uint4 kv = *(const uint4*)&sK[buf][(nn * 8 + g) * 16 + c * 4];
                mma_bf16(sc[n], qh, kv.x, kv.y);
                mma_bf16(sc[n], qlo, kv.x, kv.y);
                mma_bf16(sc[n], qh, kv.z, kv.w);
            }

            if (kt == 0 && ch == 0) {
                // per-row reference max over first 32 keys (range safety only)
                float mx0 = sc[0][0], mx1 = sc[0][2];
                #pragma unroll
                for (int n = 0; n < 4; ++n) {
                    mx0 = fmaxf(mx0, fmaxf(sc[n][0], sc[n][1]));
                    mx1 = fmaxf(mx1, fmaxf(sc[n][2], sc[n][3]));
                }
                mx0 = fmaxf(mx0, __shfl_xor_sync(0xffffffffu, mx0, 1));
                mx0 = fmaxf(mx0, __shfl_xor_sync(0xffffffffu, mx0, 2));
                mx1 = fmaxf(mx1, __shfl_xor_sync(0xffffffffu, mx1, 1));
                mx1 = fmaxf(mx1, __shfl_xor_sync(0xffffffffu, mx1, 2));
                m0 = mx0; m1 = mx1;
            }

            // ---- exp + convert ----
            #pragma unroll
            for (int n = 0; n < 4; ++n) {
                sc[n][0] = ex2f(sc[n][0] - m0);
                sc[n][1] = ex2f(sc[n][1] - m0);
                sc[n][2] = ex2f(sc[n][2] - m1);
                sc[n][3] = ex2f(sc[n][3] - m1);
            }
            u32 pf[2][4];
            #pragma unroll
            for (int k2 = 0; k2 < 2; ++k2) {
                pf[k2][0] = cvt_bf16x2(sc[2*k2][0],   sc[2*k2][1]);
                pf[k2][1] = cvt_bf16x2(sc[2*k2][2],   sc[2*k2][3]);
                pf[k2][2] = cvt_bf16x2(sc[2*k2+1][0], sc[2*k2+1][1]);
                pf[k2][3] = cvt_bf16x2(sc[2*k2+1][2], sc[2*k2+1][3]);
            }

            // ---- PV: 2 kk, ones column accumulates l ----
            #pragma unroll
            for (int k2 = 0; k2 < 2; ++k2) {
                const int kk = ch * 2 + k2;
                const uint4 v0 = *(const uint4*)&sV[buf][(kk * 64 + g * 4 + c) * 4];
                const uint4 v1 = *(const uint4*)&sV[buf][(kk * 64 + 32 + g * 4 + c) * 4];
                mma_bf16(o[0], pf[k2], v0.x, v0.y);
                mma_bf16(o[0], pf[k2], v0.z, v0.w);
                mma_bf16(o[1], pf[k2], v1.x, v1.y);
                mma_bf16(o[1], pf[k2], v1.z, v1.w);
                mma_bf16(o[2], pf[k2], b_one, b_one);
            }
        }
        // no trailing barrier: next-tile writes target buf^1 and are issued
        // only after the next top-of-loop barrier.
    }

    const float l0 = __shfl_sync(0xffffffffu, o[2][0], lane & ~3);
    const float l1 = __shfl_sync(0xffffffffu, o[2][2], lane & ~3);
    const float i0 = 1.0f / l0, i1 = 1.0f / l1;
    const int b = bh >> 3, h = bh & 7;
    const int s0 = rowbase + g, s1 = rowbase + g + 8;
    #pragma unroll
    for (int n = 0; n < 2; ++n) {
        const int col = h * 16 + n * 8 + 2 * c;
        float2 v0 = make_float2(o[n][0] * i0, o[n][1] * i0);
        float2 v1 = make_float2(o[n][2] * i1, o[n][3] * i1);
        *(float2*)&g_a[((size_t)b * Sq + s0) * Eq + col] = v0;
        *(float2*)&g_a[((size_t)b * Sq + s1) * Eq + col] = v1;
    }
}

// ---------------------------------------------------------------------------
// Launch. Inputs: x, Wk, Wq, Wv, Wp, bp. Output: float32.
// ---------------------------------------------------------------------------
#define GEMM_SMEM (2 * 128 * 68 * 4)
#define PROJ_SMEM (2 * 64 * 68 * 4)

extern "C" void kernel_launch(void* const* d_in, const int* in_sizes, int n_in,
                              void* d_out, int out_size)
{
    const float* x  = (const float*)d_in[0];
    const float* Wk = (const float*)d_in[1];
    const float* Wq = (const float*)d_in[2];
    const float* Wv = (const float*)d_in[3];
    const float* Wp = (const float*)d_in[4];
    const float* bp = (const float*)d_in[5];
    float* out = (float*)d_out;

    cudaFuncSetAttribute(hmma_qkv, cudaFuncAttributeMaxDynamicSharedMemorySize, GEMM_SMEM);
    cudaFuncSetAttribute(hmma_proj, cudaFuncAttributeMaxDynamicSharedMemorySize, PROJ_SMEM);

    split_w<<<128, 256>>>(Wq, Wk, Wv, Wp);
    hmma_qkv<<<dim3(BSROWS / 128, 3), 256, GEMM_SMEM>>>(x);
    attn_mma<<<dim3(Sq / 128, NBH), 256>>>();
    hmma_proj<<<dim3(BSROWS / 128, 2), 256, PROJ_SMEM>>>(bp, out);
}